// round 15
// baseline (speedup 1.0000x reference)
#include <cuda_runtime.h>
#include <cuda_fp16.h>
#include <math.h>
#include <stdint.h>

#define SQ   2640
#define TF   880
#define NHH  12
#define HDD  128
#define NEL  (SQ*NHH*HDD)
#define QSC   0.12751744729777468f   // (1/sqrt(128)) * log2(e)

#define BM 64
#define BN 64
#define NTH 128
#define KTILE_B 16384          // 64 rows x 256 B (fp16)
#define VTILE_B 16384          // 128 d x 128 B
#define STAGE_B (KTILE_B + VTILE_B)
#define NSTG 3
#define ONESH2 0x3C003C00u     // half2(1.0, 1.0)

#define NPRE 3960              // preproc blocks: SQ*NHH*32/256
#define NVT  (83*4*12)         // vtrans blocks

// ---------------- device scratch ----------------
__device__ __half g_qrh[NHH*SQ*HDD];        // rope Q [h][s][d]  (*QSC)
__device__ __half g_krh[NHH*SQ*HDD];        // rope K
__device__ __half g_qph[NHH*SQ*HDD];        // prope Q (*QSC)
__device__ __half g_kph[NHH*SQ*HDD];        // prope K
__device__ __half g_vrh[NHH*HDD*SQ + 64];   // V^T [h][d][s]
__device__ __half g_vph[NHH*HDD*SQ + 64];   // (Pinv V)^T
__device__ float  g_P  [3][16];

// ---------------- helpers ----------------
__device__ __forceinline__ uint32_t smem_u32(const void* p) {
    return (uint32_t)__cvta_generic_to_shared(p);
}
__device__ __forceinline__ void cp_async16(uint32_t dst, const void* src) {
    asm volatile("cp.async.cg.shared.global [%0], [%1], 16;" :: "r"(dst), "l"(src));
}
#define CP_COMMIT() asm volatile("cp.async.commit_group;")

#define LDSM_X4(r0,r1,r2,r3,addr) \
    asm volatile("ldmatrix.sync.aligned.m8n8.x4.shared.b16 {%0,%1,%2,%3}, [%4];" \
        : "=r"(r0), "=r"(r1), "=r"(r2), "=r"(r3) : "r"(addr))

// f32-accumulator MMA (PV + ones-column)
#define MMA_F16(D, A, b0, b1)                                                \
  asm volatile("mma.sync.aligned.m16n8k16.row.col.f32.f16.f16.f32 "          \
    "{%0,%1,%2,%3},{%4,%5,%6,%7},{%8,%9},{%0,%1,%2,%3};"                     \
    : "+f"((D)[0]), "+f"((D)[1]), "+f"((D)[2]), "+f"((D)[3])                 \
    : "r"((A)[0]), "r"((A)[1]), "r"((A)[2]), "r"((A)[3]), "r"(b0), "r"(b1))

// f16-accumulator MMA (QK): C-frag layout == PV A-frag layout
#define MMA_F16C(D, A, b0, b1)                                               \
  asm volatile("mma.sync.aligned.m16n8k16.row.col.f16.f16.f16.f16 "          \
    "{%0,%1},{%2,%3,%4,%5},{%6,%7},{%0,%1};"                                 \
    : "+r"((D)[0]), "+r"((D)[1])                                             \
    : "r"((A)[0]), "r"((A)[1]), "r"((A)[2]), "r"((A)[3]), "r"(b0), "r"(b1))

#define EX2H2(d, s) asm("ex2.approx.f16x2 %0, %1;" : "=r"(d) : "r"(s))

// closed-form 4x4 inverse via adjugate (static indexing only -> no spills)
__device__ __forceinline__ void inv4x4(const float* m, float* inv) {
    float A2323 = m[10]*m[15] - m[11]*m[14];
    float A1323 = m[9] *m[15] - m[11]*m[13];
    float A1223 = m[9] *m[14] - m[10]*m[13];
    float A0323 = m[8] *m[15] - m[11]*m[12];
    float A0223 = m[8] *m[14] - m[10]*m[12];
    float A0123 = m[8] *m[13] - m[9] *m[12];
    float A2313 = m[6] *m[15] - m[7] *m[14];
    float A1313 = m[5] *m[15] - m[7] *m[13];
    float A1213 = m[5] *m[14] - m[6] *m[13];
    float A2312 = m[6] *m[11] - m[7] *m[10];
    float A1312 = m[5] *m[11] - m[7] *m[9];
    float A1212 = m[5] *m[10] - m[6] *m[9];
    float A0313 = m[4] *m[15] - m[7] *m[12];
    float A0213 = m[4] *m[14] - m[6] *m[12];
    float A0312 = m[4] *m[11] - m[7] *m[8];
    float A0212 = m[4] *m[10] - m[6] *m[8];
    float A0113 = m[4] *m[13] - m[5] *m[12];
    float A0112 = m[4] *m[9]  - m[5] *m[8];

    float det = m[0]*(m[5]*A2323 - m[6]*A1323 + m[7]*A1223)
              - m[1]*(m[4]*A2323 - m[6]*A0323 + m[7]*A0223)
              + m[2]*(m[4]*A1323 - m[5]*A0323 + m[7]*A0123)
              - m[3]*(m[4]*A1223 - m[5]*A0223 + m[6]*A0123);
    float rd = 1.f / det;

    inv[0]  =  rd*(m[5]*A2323 - m[6]*A1323 + m[7]*A1223);
    inv[1]  = -rd*(m[1]*A2323 - m[2]*A1323 + m[3]*A1223);
    inv[2]  =  rd*(m[1]*A2313 - m[2]*A1313 + m[3]*A1213);
    inv[3]  = -rd*(m[1]*A2312 - m[2]*A1312 + m[3]*A1212);
    inv[4]  = -rd*(m[4]*A2323 - m[6]*A0323 + m[7]*A0223);
    inv[5]  =  rd*(m[0]*A2323 - m[2]*A0323 + m[3]*A0223);
    inv[6]  = -rd*(m[0]*A2313 - m[2]*A0313 + m[3]*A0213);
    inv[7]  =  rd*(m[0]*A2312 - m[2]*A0312 + m[3]*A0212);
    inv[8]  =  rd*(m[4]*A1323 - m[5]*A0323 + m[7]*A0123);
    inv[9]  = -rd*(m[0]*A1323 - m[1]*A0323 + m[3]*A0123);
    inv[10] =  rd*(m[0]*A1313 - m[1]*A0313 + m[3]*A0113);
    inv[11] = -rd*(m[0]*A1312 - m[1]*A0312 + m[3]*A0112);
    inv[12] = -rd*(m[4]*A1223 - m[5]*A0223 + m[6]*A0123);
    inv[13] =  rd*(m[0]*A1223 - m[1]*A0223 + m[2]*A0123);
    inv[14] = -rd*(m[0]*A1213 - m[1]*A0213 + m[2]*A0113);
    inv[15] =  rd*(m[0]*A1212 - m[1]*A0212 + m[2]*A0112);
}

// ---------------- kernel 1: fused prep (adjugate P/Pinv + RoPE/proj QK + V transpose) ----------------
__global__ __launch_bounds__(256) void prep_kernel(
        const float4* __restrict__ q, const float4* __restrict__ k,
        const float* __restrict__ v,
        const float* __restrict__ cosb, const float* __restrict__ sinb,
        const float* __restrict__ vm, const float* __restrict__ Ks) {
    __shared__ float sP[3][16], sPi[3][16];
    __shared__ float smv[32][33];
    int tid = threadIdx.x;
    if (tid < 3) {
        int f = tid;
        float P[16], Pi[16];
        #pragma unroll
        for (int i = 0; i < 3; i++)
            #pragma unroll
            for (int j = 0; j < 4; j++) {
                float s = 0.f;
                #pragma unroll
                for (int k2 = 0; k2 < 3; k2++)
                    s += Ks[f*9 + i*3 + k2] * vm[f*16 + k2*4 + j];
                P[i*4 + j] = s;
            }
        #pragma unroll
        for (int j = 0; j < 4; j++) P[12 + j] = vm[f*16 + 12 + j];
        inv4x4(P, Pi);
        #pragma unroll
        for (int i = 0; i < 16; i++) { sP[f][i] = P[i]; sPi[f][i] = Pi[i]; }
        if (blockIdx.x == 0)
            #pragma unroll
            for (int i = 0; i < 16; i++) g_P[f][i] = P[i];
    }
    __syncthreads();

    if (blockIdx.x < NPRE) {
        int t = blockIdx.x*256 + tid;
        int d4 = t & 31;
        int h  = (t >> 5) % NHH;
        int s  = t / (NHH*32);
        int f  = s / TF;

        float4 q4 = q[(s*NHH + h)*32 + d4];
        float4 k4 = k[(s*NHH + h)*32 + d4];
        float c0 = cosb[s*64 + 2*d4], c1 = cosb[s*64 + 2*d4 + 1];
        float s0 = sinb[s*64 + 2*d4], s1 = sinb[s*64 + 2*d4 + 1];

        float4 qr, kr;
        qr.x = (q4.x*c0 - q4.y*s0)*QSC; qr.y = (q4.y*c0 + q4.x*s0)*QSC;
        qr.z = (q4.z*c1 - q4.w*s1)*QSC; qr.w = (q4.w*c1 + q4.z*s1)*QSC;
        kr.x = k4.x*c0 - k4.y*s0;       kr.y = k4.y*c0 + k4.x*s0;
        kr.z = k4.z*c1 - k4.w*s1;       kr.w = k4.w*c1 + k4.z*s1;

        const float* P  = sP[f];
        const float* Pi = sPi[f];
        float4 qp, kp;
        qp.x = (P[0] *q4.x + P[1] *q4.y + P[2] *q4.z + P[3] *q4.w)*QSC;
        qp.y = (P[4] *q4.x + P[5] *q4.y + P[6] *q4.z + P[7] *q4.w)*QSC;
        qp.z = (P[8] *q4.x + P[9] *q4.y + P[10]*q4.z + P[11]*q4.w)*QSC;
        qp.w = (P[12]*q4.x + P[13]*q4.y + P[14]*q4.z + P[15]*q4.w)*QSC;
        kp.x = Pi[0]*k4.x + Pi[4]*k4.y + Pi[8] *k4.z + Pi[12]*k4.w;  // Pinv^T @ k
        kp.y = Pi[1]*k4.x + Pi[5]*k4.y + Pi[9] *k4.z + Pi[13]*k4.w;
        kp.z = Pi[2]*k4.x + Pi[6]*k4.y + Pi[10]*k4.z + Pi[14]*k4.w;
        kp.w = Pi[3]*k4.x + Pi[7]*k4.y + Pi[11]*k4.z + Pi[15]*k4.w;

        size_t o = ((size_t)h*SQ + s)*HDD + d4*4;
        *(__half2*)(g_qrh + o)     = __floats2half2_rn(qr.x, qr.y);
        *(__half2*)(g_qrh + o + 2) = __floats2half2_rn(qr.z, qr.w);
        *(__half2*)(g_krh + o)     = __floats2half2_rn(kr.x, kr.y);
        *(__half2*)(g_krh + o + 2) = __floats2half2_rn(kr.z, kr.w);
        *(__half2*)(g_qph + o)     = __floats2half2_rn(qp.x, qp.y);
        *(__half2*)(g_qph + o + 2) = __floats2half2_rn(qp.z, qp.w);
        *(__half2*)(g_kph + o)     = __floats2half2_rn(kp.x, kp.y);
        *(__half2*)(g_kph + o + 2) = __floats2half2_rn(kp.z, kp.w);
    } else {
        int vb = blockIdx.x - NPRE;
        int s0i = vb % 83;
        int rest = vb / 83;
        int d0 = (rest & 3) * 32;
        int h  = rest >> 2;
        int s0 = s0i * 32;
        int tx = tid & 31, ty = tid >> 5;

        for (int i = ty; i < 32; i += 8) {
            int s = s0 + i;
            smv[i][tx] = (s < SQ) ? v[((size_t)s*NHH + h)*HDD + d0 + tx] : 0.f;
        }
        __syncthreads();

        int sw = s0 + tx;
        if (sw < SQ) {
            const float* Pi = sPi[sw / TF];
            for (int i = ty; i < 32; i += 8) {
                int d = d0 + i;
                int gb = i & ~3, a = i & 3;
                float vp = Pi[a*4+0]*smv[tx][gb]   + Pi[a*4+1]*smv[tx][gb+1]
                         + Pi[a*4+2]*smv[tx][gb+2] + Pi[a*4+3]*smv[tx][gb+3];
                g_vrh[((size_t)h*HDD + d)*SQ + sw] = __float2half_rn(smv[tx][i]);
                g_vph[((size_t)h*HDD + d)*SQ + sw] = __float2half_rn(vp);
            }
        }
    }
}

// ---------------- kernel 2: fp16 flash attention, f16-acc QK, 3-stage ring ----------------
__global__ __launch_bounds__(NTH, 2) void attn_kernel(float* __restrict__ out) {
    extern __shared__ char smc[];
    uint32_t sb = smem_u32(smc);

    int kind = blockIdx.z, h = blockIdx.y;
    int row0 = (gridDim.x - 1 - blockIdx.x) * BM;   // longest blocks first
    int tid = threadIdx.x;
    int w = tid >> 5, lane = tid & 31, g = lane >> 2, a = lane & 3;
    int r8 = lane & 7, mhi = lane >> 3;
    int knp = ((mhi >> 1) << 3) + r8;   // row within matrix pair: 0..15
    int mb  = mhi & 1;                  // k-chunk parity
    int ksw = knp & 7;                  // swizzle key

    const __half* Q  = (kind ? g_qph : g_qrh) + (size_t)h*SQ*HDD;
    const __half* K  = (kind ? g_kph : g_krh) + (size_t)h*SQ*HDD;
    const __half* Vt = (kind ? g_vph : g_vrh) + (size_t)h*HDD*SQ;
    float* Out = out + (size_t)kind*NEL;

    int rw  = row0 + w*16;
    int ra  = rw + g, rb = rw + g + 8;
    int rca = min(ra, SQ-1), rcb = min(rb, SQ-1);
    int kma = (rca/TF + 1)*TF;
    int kmb = (rcb/TF + 1)*TF;
    int kmw = (min(rw, SQ-1)/TF + 1)*TF;   // warp-min mask bound
    int kend = (min(row0 + BM - 1, SQ-1)/TF + 1)*TF;
    int nt = (kend + BN - 1)/BN;

    // Q fragments (8 k16-steps x 4 regs)
    uint32_t qf[8][4];
    {
        const uint32_t* Qa = (const uint32_t*)(Q + (size_t)rca*HDD);
        const uint32_t* Qb = (const uint32_t*)(Q + (size_t)rcb*HDD);
        #pragma unroll
        for (int ks = 0; ks < 8; ks++) {
            qf[ks][0] = Qa[8*ks + a];
            qf[ks][1] = Qb[8*ks + a];
            qf[ks][2] = Qa[8*ks + a + 4];
            qf[ks][3] = Qb[8*ks + a + 4];
        }
    }

    float of[16][4];
    #pragma unroll
    for (int n = 0; n < 16; n++) { of[n][0]=0.f; of[n][1]=0.f; of[n][2]=0.f; of[n][3]=0.f; }
    float ofl[4];
    ofl[0]=0.f; ofl[1]=0.f; ofl[2]=0.f; ofl[3]=0.f;   // l accumulator (ones-column)
    uint32_t sf2[8][2];                                // f16 QK C-fragments

    auto issue_tile = [&](int j0, int stg) {
        uint32_t kb = sb + (uint32_t)stg*STAGE_B;
        uint32_t vb = kb + KTILE_B;
        #pragma unroll
        for (int it = 0; it < 8; it++) {           // K: 64 rows x 16 chunks
            int idx = tid + it*NTH;
            int r = idx >> 4, c = idx & 15;
            cp_async16(kb + (uint32_t)(r*256 + ((c ^ (r & 7)) << 4)),
                       K + (size_t)min(j0 + r, SQ-1)*HDD + c*8);
        }
        #pragma unroll
        for (int it = 0; it < 8; it++) {           // V: 128 d x 8 chunks
            int idx = tid + it*NTH;
            int d = idx >> 3, c = idx & 7;
            cp_async16(vb + (uint32_t)(d*128 + ((c ^ (d & 7)) << 4)),
                       Vt + (size_t)d*SQ + min(j0 + c*8, SQ-8));
        }
        CP_COMMIT();
    };

    issue_tile(0, 0);
    issue_tile(BN, 1);

    // ---- prologue: QK(0) from stage 0 ----
    asm volatile("cp.async.wait_group 1;");
    __syncthreads();
    #pragma unroll
    for (int n = 0; n < 8; n++) { sf2[n][0] = 0u; sf2[n][1] = 0u; }
    {
        uint32_t kbase = sb;
        #pragma unroll
        for (int i = 0; i < 32; i++) {
            int ks = i >> 2, nb2 = i & 3;
            uint32_t b0, b1, b2, b3;
            uint32_t addr = kbase + (uint32_t)(nb2*4096 + knp*256
                          + ((((ks << 1) | mb) ^ ksw) << 4));
            LDSM_X4(b0, b1, b2, b3, addr);
            MMA_F16C(sf2[2*nb2],     qf[ks], b0, b1);
            MMA_F16C(sf2[2*nb2 + 1], qf[ks], b2, b3);
        }
    }

    int stv = 0;   // stage of tile j (V side); K(j+1) is stage (stv+1)%3
    for (int j = 0; j < nt; j++) {
        // ---- softmax(j): mask (rare) + ex2.f16x2 straight on C-frags ----
        int j0 = j*BN;
        uint32_t pa[4][4];
        if (j0 + BN <= kmw) {                 // interior tile: no masking
            #pragma unroll
            for (int kt = 0; kt < 4; kt++) {
                EX2H2(pa[kt][0], sf2[2*kt][0]);
                EX2H2(pa[kt][1], sf2[2*kt][1]);
                EX2H2(pa[kt][2], sf2[2*kt + 1][0]);
                EX2H2(pa[kt][3], sf2[2*kt + 1][1]);
            }
        } else {
            #pragma unroll
            for (int nb = 0; nb < 8; nb++) {
                int c0 = j0 + nb*8 + 2*a;
                uint32_t xa = sf2[nb][0];   // rows g   : cols c0, c0+1
                uint32_t xb = sf2[nb][1];   // rows g+8 : cols c0, c0+1
                if (c0     >= kma) xa = (xa & 0xFFFF0000u) | 0x0000FC00u;
                if (c0 + 1 >= kma) xa = (xa & 0x0000FFFFu) | 0xFC000000u;
                if (c0     >= kmb) xb = (xb & 0xFFFF0000u) | 0x0000FC00u;
                if (c0 + 1 >= kmb) xb = (xb & 0x0000FFFFu) | 0xFC000000u;
                int kt = nb >> 1;
                int sl = (nb & 1) << 1;
                EX2H2(pa[kt][sl],     xa);
                EX2H2(pa[kt][sl + 1], xb);
            }
        }

        // ---- tile j+1 arrived (issued a full iteration ago); ONE barrier ----
        asm volatile("cp.async.wait_group 0;");
        __syncthreads();

        // ---- prefetch tile j+2 into the idle ring slot ----
        int jn = j + 2;
        if (jn < nt) {
            int stn = stv + 2; if (stn >= NSTG) stn -= NSTG;
            issue_tile(jn*BN, stn);
        }

        bool doqk = (j + 1 < nt);
        if (doqk) {
            #pragma unroll
            for (int n = 0; n < 8; n++) { sf2[n][0] = 0u; sf2[n][1] = 0u; }
        }
        int stk = stv + 1; if (stk >= NSTG) stk -= NSTG;
        uint32_t vbase = sb + (uint32_t)stv*STAGE_B + KTILE_B;        // V(j)
        uint32_t kbase = sb + (uint32_t)stk*STAGE_B;                  // K(j+1)

        // ---- interleaved PV(j) ⊗ QK(j+1); ones-column accumulates l ----
        #pragma unroll
        for (int i = 0; i < 32; i++) {
            {
                int kt = i >> 3, db2 = i & 7;
                uint32_t b0, b1, b2, b3;
                uint32_t addr = vbase + (uint32_t)(db2*2048 + knp*128
                              + ((((kt << 1) | mb) ^ ksw) << 4));
                LDSM_X4(b0, b1, b2, b3, addr);
                MMA_F16(of[2*db2],     pa[kt], b0, b1);
                MMA_F16(of[2*db2 + 1], pa[kt], b2, b3);
                if (db2 == 7) MMA_F16(ofl, pa[kt], ONESH2, ONESH2);   // l += row-sum(P)
            }
            if (doqk) {
                int ks = i >> 2, nb2 = i & 3;
                uint32_t c0, c1, c2, c3;
                uint32_t addr = kbase + (uint32_t)(nb2*4096 + knp*256
                              + ((((ks << 1) | mb) ^ ksw) << 4));
                LDSM_X4(c0, c1, c2, c3, addr);
                MMA_F16C(sf2[2*nb2],     qf[ks], c0, c1);
                MMA_F16C(sf2[2*nb2 + 1], qf[ks], c2, c3);
            }
        }

        stv = stk;
    }

    // ---- epilogue (l from the ones-column accumulator) ----
    float li0 = 1.f / ofl[0], li1 = 1.f / ofl[2];

    if (kind == 0) {
        if (ra < SQ) {
            float* da = Out + (size_t)ra*(NHH*HDD) + h*HDD;
            #pragma unroll
            for (int n = 0; n < 16; n++)
                *(float2*)(da + n*8 + 2*a) = make_float2(of[n][0]*li0, of[n][1]*li0);
        }
        if (rb < SQ) {
            float* db = Out + (size_t)rb*(NHH*HDD) + h*HDD;
            #pragma unroll
            for (int n = 0; n < 16; n++)
                *(float2*)(db + n*8 + 2*a) = make_float2(of[n][2]*li1, of[n][3]*li1);
        }
    } else {
        // project with P: exchange partner half of each 4-group via lane^1
        const float* Pa = g_P[rca / TF];
        const float* Pb = g_P[rcb / TF];
        int r0 = (a & 1) * 2;
        bool low = (a & 1) == 0;
        float* da = Out + (size_t)rca*(NHH*HDD) + h*HDD;
        float* db = Out + (size_t)rcb*(NHH*HDD) + h*HDD;
        #pragma unroll
        for (int n = 0; n < 16; n++) {
            float x0 = of[n][0]*li0, x1 = of[n][1]*li0;
            float x2 = of[n][2]*li1, x3 = of[n][3]*li1;
            float y0 = __shfl_xor_sync(0xffffffffu, x0, 1);
            float y1 = __shfl_xor_sync(0xffffffffu, x1, 1);
            float y2 = __shfl_xor_sync(0xffffffffu, x2, 1);
            float y3 = __shfl_xor_sync(0xffffffffu, x3, 1);
            float va0 = low ? x0 : y0, va1 = low ? x1 : y1;
            float va2 = low ? y0 : x0, va3 = low ? y1 : x1;
            float vb0 = low ? x2 : y2, vb1 = low ? x3 : y3;
            float vb2 = low ? y2 : x2, vb3 = low ? y3 : x3;
            if (ra < SQ) {
                float o0 = Pa[r0*4+0]*va0 + Pa[r0*4+1]*va1 + Pa[r0*4+2]*va2 + Pa[r0*4+3]*va3;
                float o1 = Pa[r0*4+4]*va0 + Pa[r0*4+5]*va1 + Pa[r0*4+6]*va2 + Pa[r0*4+7]*va3;
                *(float2*)(da + n*8 + 2*a) = make_float2(o0, o1);
            }
            if (rb < SQ) {
                float o0 = Pb[r0*4+0]*vb0 + Pb[r0*4+1]*vb1 + Pb[r0*4+2]*vb2 + Pb[r0*4+3]*vb3;
                float o1 = Pb[r0*4+4]*vb0 + Pb[r0*4+5]*vb1 + Pb[r0*4+6]*vb2 + Pb[r0*4+7]*vb3;
                *(float2*)(db + n*8 + 2*a) = make_float2(o0, o1);
            }
        }
    }
}

// ---------------- launch ----------------
extern "C" void kernel_launch(void* const* d_in, const int* in_sizes, int n_in,
                              void* d_out, int out_size) {
    const float* q    = (const float*)d_in[0];
    const float* k    = (const float*)d_in[1];
    const float* v    = (const float*)d_in[2];
    const float* cosb = (const float*)d_in[3];
    const float* sinb = (const float*)d_in[4];
    const float* vm   = (const float*)d_in[5];
    const float* Ks   = (const float*)d_in[6];
    float* out = (float*)d_out;

    const int smem_bytes = NSTG*STAGE_B;   // 98,304 B
    cudaFuncSetAttribute(attn_kernel, cudaFuncAttributeMaxDynamicSharedMemorySize, smem_bytes);

    prep_kernel<<<NPRE + NVT, 256>>>((const float4*)q, (const float4*)k, v, cosb, sinb, vm, Ks);
    attn_kernel<<<dim3((SQ + BM - 1)/BM, NHH, 2), NTH, smem_bytes>>>(out);
}

// round 16
// speedup vs baseline: 1.0435x; 1.0435x over previous
#include <cuda_runtime.h>
#include <cuda_fp16.h>
#include <math.h>
#include <stdint.h>

#define SQ   2640
#define TF   880
#define NHH  12
#define HDD  128
#define NEL  (SQ*NHH*HDD)
#define QSC   0.12751744729777468f   // (1/sqrt(128)) * log2(e)

#define BM 64
#define BN 64
#define NTH 128
#define KTILE_B 16384          // 64 rows x 256 B (fp16)
#define VTILE_B 16384          // 128 d x 128 B
#define STAGE_B (KTILE_B + VTILE_B)
#define NSTG 3
#define ONESH2 0x3C003C00u     // half2(1.0, 1.0)

#define NPRE 3960              // preproc blocks: SQ*NHH*32/256
#define NVT  (83*4*12)         // vtrans blocks

// ---------------- device scratch ----------------
__device__ __half g_qrh[NHH*SQ*HDD];        // rope Q [h][s][d]  (*QSC)
__device__ __half g_krh[NHH*SQ*HDD];        // rope K
__device__ __half g_qph[NHH*SQ*HDD];        // prope Q (*QSC)
__device__ __half g_kph[NHH*SQ*HDD];        // prope K
__device__ __half g_vrh[NHH*HDD*SQ + 64];   // V^T [h][d][s]
__device__ __half g_vph[NHH*HDD*SQ + 64];   // (Pinv V)^T
__device__ float  g_P  [3][16];

// ---------------- helpers ----------------
__device__ __forceinline__ uint32_t smem_u32(const void* p) {
    return (uint32_t)__cvta_generic_to_shared(p);
}
__device__ __forceinline__ void cp_async16(uint32_t dst, const void* src) {
    asm volatile("cp.async.cg.shared.global [%0], [%1], 16;" :: "r"(dst), "l"(src));
}
#define CP_COMMIT() asm volatile("cp.async.commit_group;")

#define LDSM_X4(r0,r1,r2,r3,addr) \
    asm volatile("ldmatrix.sync.aligned.m8n8.x4.shared.b16 {%0,%1,%2,%3}, [%4];" \
        : "=r"(r0), "=r"(r1), "=r"(r2), "=r"(r3) : "r"(addr))

#define MMA_F16(D, A, b0, b1)                                                \
  asm volatile("mma.sync.aligned.m16n8k16.row.col.f32.f16.f16.f32 "          \
    "{%0,%1,%2,%3},{%4,%5,%6,%7},{%8,%9},{%0,%1,%2,%3};"                     \
    : "+f"((D)[0]), "+f"((D)[1]), "+f"((D)[2]), "+f"((D)[3])                 \
    : "r"((A)[0]), "r"((A)[1]), "r"((A)[2]), "r"((A)[3]), "r"(b0), "r"(b1))

// half2 = exp2(half2(cvt(lo, hi)))  — one cvt + one MUFU for two p's, pre-packed
__device__ __forceinline__ uint32_t exp2_pack(float lo, float hi) {
    uint32_t h, r;
    asm("cvt.rn.f16x2.f32 %0, %1, %2;" : "=r"(h) : "f"(hi), "f"(lo));
    asm("ex2.approx.f16x2 %0, %1;" : "=r"(r) : "r"(h));
    return r;
}

// closed-form 4x4 inverse via adjugate (static indexing only -> no spills)
__device__ __forceinline__ void inv4x4(const float* m, float* inv) {
    float A2323 = m[10]*m[15] - m[11]*m[14];
    float A1323 = m[9] *m[15] - m[11]*m[13];
    float A1223 = m[9] *m[14] - m[10]*m[13];
    float A0323 = m[8] *m[15] - m[11]*m[12];
    float A0223 = m[8] *m[14] - m[10]*m[12];
    float A0123 = m[8] *m[13] - m[9] *m[12];
    float A2313 = m[6] *m[15] - m[7] *m[14];
    float A1313 = m[5] *m[15] - m[7] *m[13];
    float A1213 = m[5] *m[14] - m[6] *m[13];
    float A2312 = m[6] *m[11] - m[7] *m[10];
    float A1312 = m[5] *m[11] - m[7] *m[9];
    float A1212 = m[5] *m[10] - m[6] *m[9];
    float A0313 = m[4] *m[15] - m[7] *m[12];
    float A0213 = m[4] *m[14] - m[6] *m[12];
    float A0312 = m[4] *m[11] - m[7] *m[8];
    float A0212 = m[4] *m[10] - m[6] *m[8];
    float A0113 = m[4] *m[13] - m[5] *m[12];
    float A0112 = m[4] *m[9]  - m[5] *m[8];

    float det = m[0]*(m[5]*A2323 - m[6]*A1323 + m[7]*A1223)
              - m[1]*(m[4]*A2323 - m[6]*A0323 + m[7]*A0223)
              + m[2]*(m[4]*A1323 - m[5]*A0323 + m[7]*A0123)
              - m[3]*(m[4]*A1223 - m[5]*A0223 + m[6]*A0123);
    float rd = 1.f / det;

    inv[0]  =  rd*(m[5]*A2323 - m[6]*A1323 + m[7]*A1223);
    inv[1]  = -rd*(m[1]*A2323 - m[2]*A1323 + m[3]*A1223);
    inv[2]  =  rd*(m[1]*A2313 - m[2]*A1313 + m[3]*A1213);
    inv[3]  = -rd*(m[1]*A2312 - m[2]*A1312 + m[3]*A1212);
    inv[4]  = -rd*(m[4]*A2323 - m[6]*A0323 + m[7]*A0223);
    inv[5]  =  rd*(m[0]*A2323 - m[2]*A0323 + m[3]*A0223);
    inv[6]  = -rd*(m[0]*A2313 - m[2]*A0313 + m[3]*A0213);
    inv[7]  =  rd*(m[0]*A2312 - m[2]*A0312 + m[3]*A0212);
    inv[8]  =  rd*(m[4]*A1323 - m[5]*A0323 + m[7]*A0123);
    inv[9]  = -rd*(m[0]*A1323 - m[1]*A0323 + m[3]*A0123);
    inv[10] =  rd*(m[0]*A1313 - m[1]*A0313 + m[3]*A0113);
    inv[11] = -rd*(m[0]*A1312 - m[1]*A0312 + m[3]*A0112);
    inv[12] = -rd*(m[4]*A1223 - m[5]*A0223 + m[6]*A0123);
    inv[13] =  rd*(m[0]*A1223 - m[1]*A0223 + m[2]*A0123);
    inv[14] = -rd*(m[0]*A1213 - m[1]*A0213 + m[2]*A0113);
    inv[15] =  rd*(m[0]*A1212 - m[1]*A0212 + m[2]*A0112);
}

// ---------------- kernel 1: fused prep (adjugate P/Pinv + RoPE/proj QK + V transpose) ----------------
__global__ __launch_bounds__(256) void prep_kernel(
        const float4* __restrict__ q, const float4* __restrict__ k,
        const float* __restrict__ v,
        const float* __restrict__ cosb, const float* __restrict__ sinb,
        const float* __restrict__ vm, const float* __restrict__ Ks) {
    __shared__ float sP[3][16], sPi[3][16];
    __shared__ float smv[32][33];
    int tid = threadIdx.x;
    if (tid < 3) {
        int f = tid;
        float P[16], Pi[16];
        #pragma unroll
        for (int i = 0; i < 3; i++)
            #pragma unroll
            for (int j = 0; j < 4; j++) {
                float s = 0.f;
                #pragma unroll
                for (int k2 = 0; k2 < 3; k2++)
                    s += Ks[f*9 + i*3 + k2] * vm[f*16 + k2*4 + j];
                P[i*4 + j] = s;
            }
        #pragma unroll
        for (int j = 0; j < 4; j++) P[12 + j] = vm[f*16 + 12 + j];
        inv4x4(P, Pi);
        #pragma unroll
        for (int i = 0; i < 16; i++) { sP[f][i] = P[i]; sPi[f][i] = Pi[i]; }
        if (blockIdx.x == 0)
            #pragma unroll
            for (int i = 0; i < 16; i++) g_P[f][i] = P[i];
    }
    __syncthreads();

    if (blockIdx.x < NPRE) {
        // ---- preproc: RoPE + projective Q,K -> fp16 ----
        int t = blockIdx.x*256 + tid;
        int d4 = t & 31;
        int h  = (t >> 5) % NHH;
        int s  = t / (NHH*32);
        int f  = s / TF;

        float4 q4 = q[(s*NHH + h)*32 + d4];
        float4 k4 = k[(s*NHH + h)*32 + d4];
        float c0 = cosb[s*64 + 2*d4], c1 = cosb[s*64 + 2*d4 + 1];
        float s0 = sinb[s*64 + 2*d4], s1 = sinb[s*64 + 2*d4 + 1];

        float4 qr, kr;
        qr.x = (q4.x*c0 - q4.y*s0)*QSC; qr.y = (q4.y*c0 + q4.x*s0)*QSC;
        qr.z = (q4.z*c1 - q4.w*s1)*QSC; qr.w = (q4.w*c1 + q4.z*s1)*QSC;
        kr.x = k4.x*c0 - k4.y*s0;       kr.y = k4.y*c0 + k4.x*s0;
        kr.z = k4.z*c1 - k4.w*s1;       kr.w = k4.w*c1 + k4.z*s1;

        const float* P  = sP[f];
        const float* Pi = sPi[f];
        float4 qp, kp;
        qp.x = (P[0] *q4.x + P[1] *q4.y + P[2] *q4.z + P[3] *q4.w)*QSC;
        qp.y = (P[4] *q4.x + P[5] *q4.y + P[6] *q4.z + P[7] *q4.w)*QSC;
        qp.z = (P[8] *q4.x + P[9] *q4.y + P[10]*q4.z + P[11]*q4.w)*QSC;
        qp.w = (P[12]*q4.x + P[13]*q4.y + P[14]*q4.z + P[15]*q4.w)*QSC;
        kp.x = Pi[0]*k4.x + Pi[4]*k4.y + Pi[8] *k4.z + Pi[12]*k4.w;  // Pinv^T @ k
        kp.y = Pi[1]*k4.x + Pi[5]*k4.y + Pi[9] *k4.z + Pi[13]*k4.w;
        kp.z = Pi[2]*k4.x + Pi[6]*k4.y + Pi[10]*k4.z + Pi[14]*k4.w;
        kp.w = Pi[3]*k4.x + Pi[7]*k4.y + Pi[11]*k4.z + Pi[15]*k4.w;

        size_t o = ((size_t)h*SQ + s)*HDD + d4*4;
        *(__half2*)(g_qrh + o)     = __floats2half2_rn(qr.x, qr.y);
        *(__half2*)(g_qrh + o + 2) = __floats2half2_rn(qr.z, qr.w);
        *(__half2*)(g_krh + o)     = __floats2half2_rn(kr.x, kr.y);
        *(__half2*)(g_krh + o + 2) = __floats2half2_rn(kr.z, kr.w);
        *(__half2*)(g_qph + o)     = __floats2half2_rn(qp.x, qp.y);
        *(__half2*)(g_qph + o + 2) = __floats2half2_rn(qp.z, qp.w);
        *(__half2*)(g_kph + o)     = __floats2half2_rn(kp.x, kp.y);
        *(__half2*)(g_kph + o + 2) = __floats2half2_rn(kp.z, kp.w);
    } else {
        // ---- vtrans: V transpose + Pinv@V -> fp16 [h][d][s] ----
        int vb = blockIdx.x - NPRE;
        int s0i = vb % 83;
        int rest = vb / 83;
        int d0 = (rest & 3) * 32;
        int h  = rest >> 2;
        int s0 = s0i * 32;
        int tx = tid & 31, ty = tid >> 5;

        for (int i = ty; i < 32; i += 8) {
            int s = s0 + i;
            smv[i][tx] = (s < SQ) ? v[((size_t)s*NHH + h)*HDD + d0 + tx] : 0.f;
        }
        __syncthreads();

        int sw = s0 + tx;
        if (sw < SQ) {
            const float* Pi = sPi[sw / TF];
            for (int i = ty; i < 32; i += 8) {
                int d = d0 + i;
                int gb = i & ~3, a = i & 3;
                float vp = Pi[a*4+0]*smv[tx][gb]   + Pi[a*4+1]*smv[tx][gb+1]
                         + Pi[a*4+2]*smv[tx][gb+2] + Pi[a*4+3]*smv[tx][gb+3];
                g_vrh[((size_t)h*HDD + d)*SQ + sw] = __float2half_rn(smv[tx][i]);
                g_vph[((size_t)h*HDD + d)*SQ + sw] = __float2half_rn(vp);
            }
        }
    }
}

// ---------------- kernel 2: fp16 flash attention, 3-stage ring, f16x2 exp, ones-column l ----------------
__global__ __launch_bounds__(NTH, 2) void attn_kernel(float* __restrict__ out) {
    extern __shared__ char smc[];
    uint32_t sb = smem_u32(smc);

    int kind = blockIdx.z, h = blockIdx.y;
    int row0 = (gridDim.x - 1 - blockIdx.x) * BM;   // longest blocks first
    int tid = threadIdx.x;
    int w = tid >> 5, lane = tid & 31, g = lane >> 2, a = lane & 3;
    int r8 = lane & 7, mhi = lane >> 3;
    int knp = ((mhi >> 1) << 3) + r8;   // row within matrix pair: 0..15
    int mb  = mhi & 1;                  // k-chunk parity
    int ksw = knp & 7;                  // swizzle key

    const __half* Q  = (kind ? g_qph : g_qrh) + (size_t)h*SQ*HDD;
    const __half* K  = (kind ? g_kph : g_krh) + (size_t)h*SQ*HDD;
    const __half* Vt = (kind ? g_vph : g_vrh) + (size_t)h*HDD*SQ;
    float* Out = out + (size_t)kind*NEL;

    int rw  = row0 + w*16;
    int ra  = rw + g, rb = rw + g + 8;
    int rca = min(ra, SQ-1), rcb = min(rb, SQ-1);
    int kma = (rca/TF + 1)*TF;
    int kmb = (rcb/TF + 1)*TF;
    int kmw = (min(rw, SQ-1)/TF + 1)*TF;   // warp-min mask bound
    int kend = (min(row0 + BM - 1, SQ-1)/TF + 1)*TF;
    int nt = (kend + BN - 1)/BN;

    // Q fragments (8 k16-steps x 4 regs)
    uint32_t qf[8][4];
    {
        const uint32_t* Qa = (const uint32_t*)(Q + (size_t)rca*HDD);
        const uint32_t* Qb = (const uint32_t*)(Q + (size_t)rcb*HDD);
        #pragma unroll
        for (int ks = 0; ks < 8; ks++) {
            qf[ks][0] = Qa[8*ks + a];
            qf[ks][1] = Qb[8*ks + a];
            qf[ks][2] = Qa[8*ks + a + 4];
            qf[ks][3] = Qb[8*ks + a + 4];
        }
    }

    float of[16][4];
    #pragma unroll
    for (int n = 0; n < 16; n++) { of[n][0]=0.f; of[n][1]=0.f; of[n][2]=0.f; of[n][3]=0.f; }
    float ofl[4];
    ofl[0]=0.f; ofl[1]=0.f; ofl[2]=0.f; ofl[3]=0.f;   // l accumulator (ones-column)
    float sf[8][4];

    auto issue_tile = [&](int j0, int stg) {
        uint32_t kb = sb + (uint32_t)stg*STAGE_B;
        uint32_t vb = kb + KTILE_B;
        #pragma unroll
        for (int it = 0; it < 8; it++) {           // K: 64 rows x 16 chunks
            int idx = tid + it*NTH;
            int r = idx >> 4, c = idx & 15;
            cp_async16(kb + (uint32_t)(r*256 + ((c ^ (r & 7)) << 4)),
                       K + (size_t)min(j0 + r, SQ-1)*HDD + c*8);
        }
        #pragma unroll
        for (int it = 0; it < 8; it++) {           // V: 128 d x 8 chunks
            int idx = tid + it*NTH;
            int d = idx >> 3, c = idx & 7;
            cp_async16(vb + (uint32_t)(d*128 + ((c ^ (d & 7)) << 4)),
                       Vt + (size_t)d*SQ + min(j0 + c*8, SQ-8));
        }
        CP_COMMIT();
    };

    issue_tile(0, 0);
    issue_tile(BN, 1);

    // ---- prologue: QK(0) from stage 0 ----
    asm volatile("cp.async.wait_group 1;");
    __syncthreads();
    #pragma unroll
    for (int n = 0; n < 8; n++) { sf[n][0]=0.f; sf[n][1]=0.f; sf[n][2]=0.f; sf[n][3]=0.f; }
    {
        uint32_t kbase = sb;
        #pragma unroll
        for (int i = 0; i < 32; i++) {
            int ks = i >> 2, nb2 = i & 3;
            uint32_t b0, b1, b2, b3;
            uint32_t addr = kbase + (uint32_t)(nb2*4096 + knp*256
                          + ((((ks << 1) | mb) ^ ksw) << 4));
            LDSM_X4(b0, b1, b2, b3, addr);
            MMA_F16(sf[2*nb2],     qf[ks], b0, b1);
            MMA_F16(sf[2*nb2 + 1], qf[ks], b2, b3);
        }
    }

    int stv = 0;   // stage of tile j (V side); K(j+1) is stage (stv+1)%3
    for (int j = 0; j < nt; j++) {
        // ---- softmax(j): cvt->f16x2, ex2.approx.f16x2 (pre-packed P frags) ----
        int j0 = j*BN;
        uint32_t pa[4][4];
        if (j0 + BN <= kmw) {                 // interior tile: no masking
            #pragma unroll
            for (int nb = 0; nb < 8; nb++) {
                int kt = nb >> 1;
                int sl = (nb & 1) << 1;
                pa[kt][sl]     = exp2_pack(sf[nb][0], sf[nb][1]);
                pa[kt][sl + 1] = exp2_pack(sf[nb][2], sf[nb][3]);
            }
        } else {
            #pragma unroll
            for (int nb = 0; nb < 8; nb++) {
                int c0 = j0 + nb*8 + 2*a;
                float s0 = (c0     < kma) ? sf[nb][0] : -1e30f;
                float s1 = (c0 + 1 < kma) ? sf[nb][1] : -1e30f;
                float s2 = (c0     < kmb) ? sf[nb][2] : -1e30f;
                float s3 = (c0 + 1 < kmb) ? sf[nb][3] : -1e30f;
                int kt = nb >> 1;
                int sl = (nb & 1) << 1;
                pa[kt][sl]     = exp2_pack(s0, s1);
                pa[kt][sl + 1] = exp2_pack(s2, s3);
            }
        }

        // ---- tile j+1 arrived (issued a full iteration ago); ONE barrier ----
        asm volatile("cp.async.wait_group 0;");
        __syncthreads();

        // ---- prefetch tile j+2 into the idle ring slot ----
        int jn = j + 2;
        if (jn < nt) {
            int stn = stv + 2; if (stn >= NSTG) stn -= NSTG;
            issue_tile(jn*BN, stn);
        }

        bool doqk = (j + 1 < nt);
        if (doqk) {
            #pragma unroll
            for (int n = 0; n < 8; n++) { sf[n][0]=0.f; sf[n][1]=0.f; sf[n][2]=0.f; sf[n][3]=0.f; }
        }
        int stk = stv + 1; if (stk >= NSTG) stk -= NSTG;
        uint32_t vbase = sb + (uint32_t)stv*STAGE_B + KTILE_B;        // V(j)
        uint32_t kbase = sb + (uint32_t)stk*STAGE_B;                  // K(j+1)

        // ---- interleaved PV(j) ⊗ QK(j+1); ones-column accumulates l ----
        #pragma unroll
        for (int i = 0; i < 32; i++) {
            {
                int kt = i >> 3, db2 = i & 7;
                uint32_t b0, b1, b2, b3;
                uint32_t addr = vbase + (uint32_t)(db2*2048 + knp*128
                              + ((((kt << 1) | mb) ^ ksw) << 4));
                LDSM_X4(b0, b1, b2, b3, addr);
                MMA_F16(of[2*db2],     pa[kt], b0, b1);
                MMA_F16(of[2*db2 + 1], pa[kt], b2, b3);
                if (db2 == 7) MMA_F16(ofl, pa[kt], ONESH2, ONESH2);   // l += row-sum(P)
            }
            if (doqk) {
                int ks = i >> 2, nb2 = i & 3;
                uint32_t c0, c1, c2, c3;
                uint32_t addr = kbase + (uint32_t)(nb2*4096 + knp*256
                              + ((((ks << 1) | mb) ^ ksw) << 4));
                LDSM_X4(c0, c1, c2, c3, addr);
                MMA_F16(sf[2*nb2],     qf[ks], c0, c1);
                MMA_F16(sf[2*nb2 + 1], qf[ks], c2, c3);
            }
        }

        stv = stk;
    }

    // ---- epilogue (l comes straight from the ones-column accumulator) ----
    float li0 = 1.f / ofl[0], li1 = 1.f / ofl[2];

    if (kind == 0) {
        if (ra < SQ) {
            float* da = Out + (size_t)ra*(NHH*HDD) + h*HDD;
            #pragma unroll
            for (int n = 0; n < 16; n++)
                *(float2*)(da + n*8 + 2*a) = make_float2(of[n][0]*li0, of[n][1]*li0);
        }
        if (rb < SQ) {
            float* db = Out + (size_t)rb*(NHH*HDD) + h*HDD;
            #pragma unroll
            for (int n = 0; n < 16; n++)
                *(float2*)(db + n*8 + 2*a) = make_float2(of[n][2]*li1, of[n][3]*li1);
        }
    } else {
        // project with P: exchange partner half of each 4-group via lane^1
        const float* Pa = g_P[rca / TF];
        const float* Pb = g_P[rcb / TF];
        int r0 = (a & 1) * 2;
        bool low = (a & 1) == 0;
        float* da = Out + (size_t)rca*(NHH*HDD) + h*HDD;
        float* db = Out + (size_t)rcb*(NHH*HDD) + h*HDD;
        #pragma unroll
        for (int n = 0; n < 16; n++) {
            float x0 = of[n][0]*li0, x1 = of[n][1]*li0;
            float x2 = of[n][2]*li1, x3 = of[n][3]*li1;
            float y0 = __shfl_xor_sync(0xffffffffu, x0, 1);
            float y1 = __shfl_xor_sync(0xffffffffu, x1, 1);
            float y2 = __shfl_xor_sync(0xffffffffu, x2, 1);
            float y3 = __shfl_xor_sync(0xffffffffu, x3, 1);
            float va0 = low ? x0 : y0, va1 = low ? x1 : y1;
            float va2 = low ? y0 : x0, va3 = low ? y1 : x1;
            float vb0 = low ? x2 : y2, vb1 = low ? x3 : y3;
            float vb2 = low ? y2 : x2, vb3 = low ? y3 : x3;
            if (ra < SQ) {
                float o0 = Pa[r0*4+0]*va0 + Pa[r0*4+1]*va1 + Pa[r0*4+2]*va2 + Pa[r0*4+3]*va3;
                float o1 = Pa[r0*4+4]*va0 + Pa[r0*4+5]*va1 + Pa[r0*4+6]*va2 + Pa[r0*4+7]*va3;
                *(float2*)(da + n*8 + 2*a) = make_float2(o0, o1);
            }
            if (rb < SQ) {
                float o0 = Pb[r0*4+0]*vb0 + Pb[r0*4+1]*vb1 + Pb[r0*4+2]*vb2 + Pb[r0*4+3]*vb3;
                float o1 = Pb[r0*4+4]*vb0 + Pb[r0*4+5]*vb1 + Pb[r0*4+6]*vb2 + Pb[r0*4+7]*vb3;
                *(float2*)(db + n*8 + 2*a) = make_float2(o0, o1);
            }
        }
    }
}

// ---------------- launch ----------------
extern "C" void kernel_launch(void* const* d_in, const int* in_sizes, int n_in,
                              void* d_out, int out_size) {
    const float* q    = (const float*)d_in[0];
    const float* k    = (const float*)d_in[1];
    const float* v    = (const float*)d_in[2];
    const float* cosb = (const float*)d_in[3];
    const float* sinb = (const float*)d_in[4];
    const float* vm   = (const float*)d_in[5];
    const float* Ks   = (const float*)d_in[6];
    float* out = (float*)d_out;

    const int smem_bytes = NSTG*STAGE_B;   // 98,304 B
    cudaFuncSetAttribute(attn_kernel, cudaFuncAttributeMaxDynamicSharedMemorySize, smem_bytes);

    prep_kernel<<<NPRE + NVT, 256>>>((const float4*)q, (const float4*)k, v, cosb, sinb, vm, Ks);
    attn_kernel<<<dim3((SQ + BM - 1)/BM, NHH, 2), NTH, smem_bytes>>>(out);
}